// round 5
// baseline (speedup 1.0000x reference)
#include <cuda_runtime.h>
#include <cstdint>

#define NLEV 5
#define NTOT 3800
#define NWORDS 60
#define CAND_MAX 4096
#define CH 16384

__constant__ int c_bcum[NLEV + 1] = {0, 196, 245, 258, 262, 263};
__constant__ int c_elems[NLEV]    = {3200000, 800000, 200000, 51200, 12800};
__constant__ int c_k[NLEV]        = {1000, 1000, 1000, 640, 160};
__constant__ int c_obase[NLEV]    = {0, 1000, 2000, 3000, 3640};

struct Ptrs { const float* cls[NLEV]; const float* ctn[NLEV]; const float* box[NLEV]; };

__device__ unsigned int       g_histA[NLEV][4096];
__device__ unsigned int       g_histB[NLEV][4096];
__device__ unsigned int       g_thrA[NLEV];
__device__ unsigned int       g_cumA[NLEV];
__device__ unsigned int       g_thr24[NLEV];
__device__ unsigned int       g_candCount[NLEV];
__device__ unsigned long long g_cand[NLEV][CAND_MAX];
__device__ float              g_scoresv[NTOT];
__device__ int                g_labelsv[NTOT];
__device__ unsigned char      g_validv[NTOT];
__device__ float4             g_boxesv[NTOT];
__device__ int                g_order[NTOT];
__device__ unsigned char      g_valid_o[NTOT];
__device__ float4             g_boxo[NTOT];
__device__ unsigned long long g_mask[NTOT * NWORDS];
__device__ unsigned char      g_keep[NTOT];

// Bit-exact replica of libdevice __nv_expf's in-range path (valid |a| < 87.3;
// our arguments satisfy |a| <~ 7). Explicit __fmaf_rn everywhere so
// --use_fast_math cannot degrade it to __expf.
__device__ __forceinline__ float nv_expf(float a) {
    float j = __fmaf_rn(1.442695f, a, 12582912.0f);   // 0x1.715476p0, 0x1.8p23
    j = __fsub_rn(j, 12582912.0f);
    float f = __fmaf_rn(j, -6.93145752e-1f, a);        // -0x1.62e400p-1 (ln2_hi)
    f = __fmaf_rn(j, -1.42860677e-6f, f);              // -0x1.7f7d1cp-20 (ln2_lo)
    float r =            1.37805939e-3f;               // 0x1.694000p-10
    r = __fmaf_rn(r, f, 8.37312452e-3f);               // 0x1.125edcp-7
    r = __fmaf_rn(r, f, 4.16695364e-2f);               // 0x1.555b5ap-5
    r = __fmaf_rn(r, f, 1.66664720e-1f);               // 0x1.555450p-3
    r = __fmaf_rn(r, f, 4.99999851e-1f);               // 0x1.fffff6p-2
    r = __fmaf_rn(r, f, 1.00000000e+0f);
    r = __fmaf_rn(r, f, 1.00000000e+0f);
    int i = (int)j;
    float s = __int_as_float((i << 23) + 0x3f800000);  // exact 2^i scale (in range)
    return __fmul_rn(r, s);
}
// XLA logistic expansion: 1 / (1 + exp(-x)), each op correctly rounded.
__device__ __forceinline__ float ref_sigmoid(float x) {
    return __fdiv_rn(1.0f, __fadd_rn(1.0f, nv_expf(-x)));
}
__device__ __forceinline__ float ref_score(float c, float t) {
    return __fsqrt_rn(__fmul_rn(ref_sigmoid(c), ref_sigmoid(t)));
}

__device__ __forceinline__ void block_range(int b, int& l, int& s, int& e) {
    l = NLEV - 1;
    while (b < c_bcum[l]) l--;
    s = (b - c_bcum[l]) * CH;
    e = min(s + CH, c_elems[l]);
}

__global__ void k_init() {
    int i = blockIdx.x * blockDim.x + threadIdx.x, st = gridDim.x * blockDim.x;
    unsigned* a = &g_histA[0][0]; unsigned* b = &g_histB[0][0];
    for (int t = i; t < NLEV * 4096; t += st) { a[t] = 0; b[t] = 0; }
    if (i < NLEV) g_candCount[i] = 0;
}

__global__ void k_histA(Ptrs p) {
    int l, s, e; block_range(blockIdx.x, l, s, e);
    const float* __restrict__ cls = p.cls[l];
    const float* __restrict__ ctn = p.ctn[l];
    __shared__ unsigned sh[4096];
    for (int i = threadIdx.x; i < 4096; i += blockDim.x) sh[i] = 0;
    __syncthreads();
    for (int i = s + threadIdx.x; i < e; i += blockDim.x) {
        unsigned bits = __float_as_uint(ref_score(cls[i], ctn[i / 80]));
        atomicAdd(&sh[bits >> 20], 1u);
    }
    __syncthreads();
    for (int i = threadIdx.x; i < 4096; i += blockDim.x)
        if (sh[i]) atomicAdd(&g_histA[l][i], sh[i]);
}

__global__ void k_scan(int phase) {
    __shared__ unsigned ss[256];
    int t = threadIdx.x;
    for (int l = 0; l < NLEV; l++) {
        const unsigned* h = phase ? g_histB[l] : g_histA[l];
        unsigned s = 0;
        #pragma unroll
        for (int q = 0; q < 16; q++) s += h[t * 16 + q];
        ss[t] = s;
        __syncthreads();
        if (t == 0) {
            unsigned need = phase ? ((unsigned)c_k[l] - g_cumA[l]) : (unsigned)c_k[l];
            unsigned cum = 0; int seg = 255;
            for (; seg > 0; seg--) { if (cum + ss[seg] >= need) break; cum += ss[seg]; }
            int bin = seg * 16;
            for (int b = seg * 16 + 15; b >= seg * 16; b--) {
                unsigned cc = h[b];
                if (cum + cc >= need) { bin = b; break; }
                cum += cc;
            }
            if (!phase) { g_thrA[l] = (unsigned)bin; g_cumA[l] = cum; }
            else        g_thr24[l] = (g_thrA[l] << 12) | (unsigned)bin;
        }
        __syncthreads();
    }
}

__global__ void k_histB(Ptrs p) {
    int l, s, e; block_range(blockIdx.x, l, s, e);
    const float* __restrict__ cls = p.cls[l];
    const float* __restrict__ ctn = p.ctn[l];
    unsigned thr = g_thrA[l];
    for (int i = s + threadIdx.x; i < e; i += blockDim.x) {
        unsigned bits = __float_as_uint(ref_score(cls[i], ctn[i / 80]));
        if ((bits >> 20) == thr) atomicAdd(&g_histB[l][(bits >> 8) & 0xFFFu], 1u);
    }
}

__global__ void k_collect(Ptrs p) {
    int l, s, e; block_range(blockIdx.x, l, s, e);
    const float* __restrict__ cls = p.cls[l];
    const float* __restrict__ ctn = p.ctn[l];
    unsigned thr24 = g_thr24[l];
    for (int i = s + threadIdx.x; i < e; i += blockDim.x) {
        unsigned bits = __float_as_uint(ref_score(cls[i], ctn[i / 80]));
        if ((bits >> 8) >= thr24) {
            unsigned pos = atomicAdd(&g_candCount[l], 1u);
            if (pos < CAND_MAX)
                g_cand[l][pos] = ((unsigned long long)bits << 32) | (unsigned)(~(unsigned)i);
        }
    }
}

__device__ __forceinline__ void bitonic4096(unsigned long long* s) {
    for (int k2 = 2; k2 <= 4096; k2 <<= 1)
        for (int j = k2 >> 1; j > 0; j >>= 1) {
            __syncthreads();
            for (int i = threadIdx.x; i < 4096; i += 1024) {
                int ixj = i ^ j;
                if (ixj > i) {
                    unsigned long long a = s[i], b = s[ixj];
                    bool up = ((i & k2) == 0);
                    if (up ? (a < b) : (a > b)) { s[i] = b; s[ixj] = a; }
                }
            }
        }
    __syncthreads();
}

__global__ void k_sortlevel(Ptrs p, float* out) {
    __shared__ unsigned long long s[4096];
    int l = blockIdx.x, t = threadIdx.x;
    unsigned cnt = min(g_candCount[l], (unsigned)CAND_MAX);
    for (int i = t; i < 4096; i += 1024) s[i] = (i < (int)cnt) ? g_cand[l][i] : 0ull;
    bitonic4096(s);
    int k = c_k[l];
    const float* __restrict__ box = p.box[l];
    for (int r = t; r < k; r += 1024) {
        unsigned long long key = s[r];
        unsigned bits = (unsigned)(key >> 32);
        unsigned idx  = ~(unsigned)(key & 0xFFFFFFFFu);
        float sc = __uint_as_float(bits);
        int label = idx % 80, anchor = idx / 80;
        bool valid = sc > 0.05f;
        int g = c_obase[l] + r;
        g_scoresv[g] = valid ? sc : 0.0f;
        g_labelsv[g] = label;
        g_validv[g]  = valid ? 1 : 0;
        float4 b = *(const float4*)(box + (size_t)anchor * 4);
        float off = 2.0f * (float)label;
        g_boxesv[g] = make_float4(__fadd_rn(b.x, off), __fadd_rn(b.y, off),
                                  __fadd_rn(b.z, off), __fadd_rn(b.w, off));
        out[3800 + g] = (float)label;
        out[7600 + g * 4 + 0] = fminf(fmaxf(__fdiv_rn(b.x, 1600.0f), 0.0f), 1.0f);
        out[7600 + g * 4 + 1] = fminf(fmaxf(__fdiv_rn(b.y, 1600.0f), 0.0f), 1.0f);
        out[7600 + g * 4 + 2] = fminf(fmaxf(__fdiv_rn(b.z, 1600.0f), 0.0f), 1.0f);
        out[7600 + g * 4 + 3] = fminf(fmaxf(__fdiv_rn(b.w, 1600.0f), 0.0f), 1.0f);
    }
}

__global__ void k_sortall() {
    __shared__ unsigned long long s[4096];
    int t = threadIdx.x;
    for (int i = t; i < 4096; i += 1024)
        s[i] = (i < NTOT)
             ? (((unsigned long long)__float_as_uint(g_scoresv[i]) << 32) | (unsigned)(~(unsigned)i))
             : 0ull;
    bitonic4096(s);
    for (int r = t; r < NTOT; r += 1024) {
        int g = (int)(~(unsigned)(s[r] & 0xFFFFFFFFu));
        g_order[r] = g;
        g_valid_o[r] = g_validv[g];
        g_boxo[r] = g_boxesv[g];
    }
}

__global__ void k_mask() {
    int bx = blockIdx.x, by = blockIdx.y;
    if (bx < by) return;
    __shared__ float4 cb[64];
    __shared__ float ca[64];
    int t = threadIdx.x;
    int j0 = bx * 64 + t;
    if (j0 < NTOT) {
        float4 b = g_boxo[j0];
        cb[t] = b;
        ca[t] = __fmul_rn(fmaxf(__fsub_rn(b.z, b.x), 0.0f), fmaxf(__fsub_rn(b.w, b.y), 0.0f));
    } else { cb[t] = make_float4(-1e30f, -1e30f, -1e30f, -1e30f); ca[t] = 0.0f; }
    __syncthreads();
    int i = by * 64 + t;
    if (i >= NTOT) return;
    float4 r = g_boxo[i];
    float ra = __fmul_rn(fmaxf(__fsub_rn(r.z, r.x), 0.0f), fmaxf(__fsub_rn(r.w, r.y), 0.0f));
    unsigned long long bits = 0;
    #pragma unroll 4
    for (int c = 0; c < 64; c++) {
        int j = bx * 64 + c;
        if (j > i && j < NTOT) {
            float ix1 = fmaxf(r.x, cb[c].x), iy1 = fmaxf(r.y, cb[c].y);
            float ix2 = fminf(r.z, cb[c].z), iy2 = fminf(r.w, cb[c].w);
            float inter = __fmul_rn(fmaxf(__fsub_rn(ix2, ix1), 0.0f),
                                    fmaxf(__fsub_rn(iy2, iy1), 0.0f));
            float uni = __fsub_rn(__fadd_rn(ra, ca[c]), inter);
            float iou = __fdiv_rn(inter, fmaxf(uni, 1e-9f));
            if (iou > 0.6f) bits |= (1ull << c);
        }
    }
    g_mask[(size_t)i * NWORDS + bx] = bits;
}

__global__ void k_nms_scan() {
    __shared__ unsigned long long s_remv[NWORDS], s_keepw[NWORDS];
    __shared__ unsigned s_val32[2];
    int t = threadIdx.x;
    for (int w = t; w < NWORDS; w += 64) s_remv[w] = 0ull;
    __syncthreads();
    for (int c = 0; c < NWORDS; c++) {
        int i = c * 64 + t;
        bool v = (i < NTOT) && g_valid_o[i];
        unsigned bal = __ballot_sync(0xFFFFFFFFu, v);
        if ((t & 31) == 0) s_val32[t >> 5] = bal;
        __syncthreads();
        if (t == 0) {
            unsigned long long validw = (unsigned long long)s_val32[0] |
                                        ((unsigned long long)s_val32[1] << 32);
            unsigned long long d[64];
            #pragma unroll
            for (int b = 0; b < 64; b++) {
                int ii = c * 64 + b;
                d[b] = (ii < NTOT) ? g_mask[(size_t)ii * NWORDS + c] : 0ull;
            }
            unsigned long long rem = s_remv[c], kw = 0ull;
            #pragma unroll
            for (int b = 0; b < 64; b++) {
                if (((validw >> b) & 1ull) && !((rem >> b) & 1ull)) {
                    kw |= (1ull << b);
                    rem |= d[b];
                }
            }
            s_keepw[c] = kw;
        }
        __syncthreads();
        unsigned long long kw = s_keepw[c];
        if (t < NWORDS && t > c) {
            unsigned long long acc = 0ull;
            for (int b = 0; b < 64; b++)
                if ((kw >> b) & 1ull) acc |= g_mask[(size_t)(c * 64 + b) * NWORDS + t];
            s_remv[t] |= acc;
        }
        __syncthreads();
    }
    for (int r = t; r < NTOT; r += 64)
        g_keep[g_order[r]] = (unsigned char)((s_keepw[r >> 6] >> (r & 63)) & 1ull);
}

__global__ void k_final(float* out) {
    int g = blockIdx.x * blockDim.x + threadIdx.x;
    if (g >= NTOT) return;
    unsigned char k = g_keep[g];
    out[g] = k ? g_scoresv[g] : 0.0f;
    out[22800 + g] = (float)k;
}

extern "C" void kernel_launch(void* const* d_in, const int* in_sizes, int n_in,
                              void* d_out, int out_size) {
    Ptrs p;
    if (in_sizes[0] == 3200000) {
        for (int l = 0; l < NLEV; l++) {
            p.cls[l] = (const float*)d_in[3 * l + 0];
            p.ctn[l] = (const float*)d_in[3 * l + 1];
            p.box[l] = (const float*)d_in[3 * l + 2];
        }
    } else {
        for (int l = 0; l < NLEV; l++) {
            p.box[l] = (const float*)d_in[l];
            p.cls[l] = (const float*)d_in[5 + l];
            p.ctn[l] = (const float*)d_in[10 + l];
        }
    }
    float* out = (float*)d_out;
    k_init<<<40, 256>>>();
    k_histA<<<263, 256>>>(p);
    k_scan<<<1, 256>>>(0);
    k_histB<<<263, 256>>>(p);
    k_scan<<<1, 256>>>(1);
    k_collect<<<263, 256>>>(p);
    k_sortlevel<<<5, 1024>>>(p, out);
    k_sortall<<<1, 1024>>>();
    k_mask<<<dim3(NWORDS, NWORDS), 64>>>();
    k_nms_scan<<<1, 64>>>();
    k_final<<<15, 256>>>(out);
}